// round 16
// baseline (speedup 1.0000x reference)
#include <cuda_runtime.h>
#include <cuda_fp16.h>
#include <math.h>
#include <stdint.h>
#include <string.h>

// Problem constants
#define BB 2
#define SS 2048
#define DM 1024
#define NH 16
#define DH 64
#define DFF 2752
#define MM (BB*SS)          // 4096 rows
#define EPSV 1e-5f
#define QKVS (3*DM)

// ---------------- scratch (static __device__, no allocation) ----------------
__device__ __align__(16) __half g_xn  [MM*DM];
__device__ __align__(16) __half g_qkv [MM*QKVS];
__device__ __align__(16) __half g_attn[MM*DM];
__device__ float  g_hres[MM*DM];
__device__ __align__(16) __half g_hn  [MM*DM];
__device__ __align__(16) __half g_f3  [MM*DFF];
// transposed fp16 weights, [N,K] row-major
__device__ __align__(16) __half g_wqkvT[3*DM*DM];
__device__ __align__(16) __half g_woT[DM*DM];
__device__ __align__(16) __half g_w1T[DFF*DM];
__device__ __align__(16) __half g_w3T[DFF*DM];
__device__ __align__(16) __half g_w2T[DM*DFF];

// ---------------- helpers ----------------------------------------------------
__device__ __forceinline__ uint32_t s2u(const void* p) {
    uint32_t a;
    asm("{ .reg .u64 t; cvta.to.shared.u64 t, %1; cvt.u32.u64 %0, t; }"
        : "=r"(a) : "l"(p));
    return a;
}
__device__ __forceinline__ void cpa16(uint32_t dst, const void* src) {
    asm volatile("cp.async.cg.shared.global [%0], [%1], 16;"
                 :: "r"(dst), "l"(src) : "memory");
}
__device__ __forceinline__ void mma_f16(float* c, const uint32_t* a, const uint32_t* b) {
    asm volatile("mma.sync.aligned.m16n8k16.row.col.f32.f16.f16.f32 "
        "{%0,%1,%2,%3}, {%4,%5,%6,%7}, {%8,%9}, {%0,%1,%2,%3};"
        : "+f"(c[0]), "+f"(c[1]), "+f"(c[2]), "+f"(c[3])
        : "r"(a[0]), "r"(a[1]), "r"(a[2]), "r"(a[3]), "r"(b[0]), "r"(b[1]));
}
__device__ __forceinline__ void ldm4(uint32_t* d, uint32_t addr) {
    asm volatile("ldmatrix.sync.aligned.m8n8.x4.shared.b16 {%0,%1,%2,%3}, [%4];"
        : "=r"(d[0]), "=r"(d[1]), "=r"(d[2]), "=r"(d[3]) : "r"(addr));
}
__device__ __forceinline__ void ldm4t(uint32_t* d, uint32_t addr) {
    asm volatile("ldmatrix.sync.aligned.m8n8.x4.trans.shared.b16 {%0,%1,%2,%3}, [%4];"
        : "=r"(d[0]), "=r"(d[1]), "=r"(d[2]), "=r"(d[3]) : "r"(addr));
}
__device__ __forceinline__ uint32_t h2u(float lo, float hi) {
    uint32_t r;
    asm("cvt.rn.f16x2.f32 %0, %1, %2;" : "=r"(r) : "f"(hi), "f"(lo));
    return r;
}

// ---------------- RMSNorm (fp32 in -> fp16 out) ------------------------------
__global__ __launch_bounds__(256) void rmsnorm_h(const float* __restrict__ x,
                                                 const float* __restrict__ g,
                                                 __half* __restrict__ out) {
    int row = blockIdx.x;
    const float* xr = x + (size_t)row * DM;
    __half* orow = out + (size_t)row * DM;
    int t = threadIdx.x;
    float4 v = *(const float4*)&xr[t * 4];
    float ss = v.x*v.x + v.y*v.y + v.z*v.z + v.w*v.w;
    for (int o = 16; o > 0; o >>= 1) ss += __shfl_xor_sync(0xffffffffu, ss, o);
    __shared__ float wsum[8];
    if ((t & 31) == 0) wsum[t >> 5] = ss;
    __syncthreads();
    if (t < 8) {
        float s = wsum[t];
        for (int o = 4; o > 0; o >>= 1) s += __shfl_xor_sync(0xffu, s, o);
        if (t == 0) wsum[0] = s;
    }
    __syncthreads();
    float inv = rsqrtf(wsum[0] * (1.0f / DM) + EPSV);
    float4 gv = *(const float4*)&g[t * 4];
    ((__half2*)orow)[t*2  ] = __floats2half2_rn(v.x*inv*gv.x, v.y*inv*gv.y);
    ((__half2*)orow)[t*2+1] = __floats2half2_rn(v.z*inv*gv.z, v.w*inv*gv.w);
}

// ---------------- merged weight transpose fp32 -> fp16 [N,K], one launch -----
struct TransAll {
    const float* src[7];
    __half* dst[7];
    int R[7], C[7];
    int start[8];
};
__global__ __launch_bounds__(256) void transpose_all_k(TransAll ja) {
    __shared__ float t[32][33];
    int tile = blockIdx.x;
    int w = 0;
    while (tile >= ja.start[w + 1]) w++;
    int local = tile - ja.start[w];
    const float* in = ja.src[w];
    __half* out = ja.dst[w];
    int R = ja.R[w], C = ja.C[w];
    int tilesX = C >> 5;
    int bx = (local % tilesX) * 32, by = (local / tilesX) * 32;
    int tx = threadIdx.x & 31, ty = threadIdx.x >> 5;
    #pragma unroll
    for (int i = 0; i < 32; i += 8)
        t[ty + i][tx] = in[(size_t)(by + ty + i) * C + bx + tx];
    __syncthreads();
    #pragma unroll
    for (int i = 0; i < 32; i += 8)
        out[(size_t)(bx + ty + i) * R + by + tx] = __float2half(t[tx][ty + i]);
}

// ---------------- fp16 mma.sync GEMM (ldmatrix) ------------------------------
// C[M,N] = A[M,K] @ Wt[N,K]^T.  BM=BN=128, BK=32, 4-stage cp.async.
// EPI: 0 plain->half, 1 residual(+extra)->float
#define BKH 40
#define OPB (128*BKH*2)
#define STAGE_BYTES (2u*OPB)
#define GSMEM (4u*STAGE_BYTES)       // 81920

template <int EPI>
__global__ __launch_bounds__(256) void gemm_mma(
    const __half* __restrict__ A, const __half* __restrict__ Bw,
    const float* __restrict__ extra, void* __restrict__ Cv,
    int M_, int N_, int K_)
{
    extern __shared__ char smc[];
    uint32_t smb = s2u(smc);
    int tid = threadIdx.x, lane = tid & 31, wid = tid >> 5;
    int wm = wid & 3, wn = wid >> 2;
    int g = lane >> 2, tg = lane & 3;
    int bm = blockIdx.y * 128, bn = blockIdx.x * 128;
    int nt = K_ >> 5;

    int l15 = lane & 15, lk16 = (lane >> 4) * 16;
    int browoff = ((lane >> 4) & 1) * 8 + (lane & 7);
    int bk16 = ((lane >> 3) & 1) * 16;

    float acc[2][8][4];
    #pragma unroll
    for (int i = 0; i < 2; i++)
        #pragma unroll
        for (int j = 0; j < 8; j++)
            #pragma unroll
            for (int c = 0; c < 4; c++) acc[i][j][c] = 0.0f;

    auto load_stage = [&](int s, int t) {
        int k0 = t * 32;
        uint32_t sa = smb + s * STAGE_BYTES;
        uint32_t sbb = sa + OPB;
        #pragma unroll
        for (int i = 0; i < 2; i++) {
            int e = tid + i * 256;
            int row = e >> 2, ch = e & 3;
            cpa16(sa + row * 80 + ch * 16,
                  A + (size_t)(bm + row) * K_ + k0 + ch * 8);
            cpa16(sbb + row * 80 + ch * 16,
                  Bw + (size_t)(bn + row) * K_ + k0 + ch * 8);
        }
    };

    load_stage(0, 0); asm volatile("cp.async.commit_group;");
    if (nt > 1) load_stage(1, 1); asm volatile("cp.async.commit_group;");
    if (nt > 2) load_stage(2, 2); asm volatile("cp.async.commit_group;");

    for (int t = 0; t < nt; t++) {
        if (t + 3 < nt) load_stage((t + 3) & 3, t + 3);
        asm volatile("cp.async.commit_group;");
        asm volatile("cp.async.wait_group 3;");
        __syncthreads();

        uint32_t sA = smb + (t & 3) * STAGE_BYTES;
        uint32_t sB = sA + OPB;
        #pragma unroll
        for (int ks = 0; ks < 2; ks++) {
            uint32_t af[2][4], bf[8][2];
            ldm4(af[0], sA + (wm*32      + l15) * 80 + ks*32 + lk16);
            ldm4(af[1], sA + (wm*32 + 16 + l15) * 80 + ks*32 + lk16);
            #pragma unroll
            for (int np = 0; np < 4; np++) {
                uint32_t d[4];
                ldm4(d, sB + (wn*64 + np*16 + browoff) * 80 + ks*32 + bk16);
                bf[2*np][0] = d[0]; bf[2*np][1] = d[1];
                bf[2*np+1][0] = d[2]; bf[2*np+1][1] = d[3];
            }
            #pragma unroll
            for (int mt = 0; mt < 2; mt++)
                #pragma unroll
                for (int ntile = 0; ntile < 8; ntile++)
                    mma_f16(acc[mt][ntile], af[mt], bf[ntile]);
        }
        __syncthreads();
    }

    #pragma unroll
    for (int mt = 0; mt < 2; mt++) {
        int rr0 = bm + wm * 32 + mt * 16 + g;
        #pragma unroll
        for (int ntile = 0; ntile < 8; ntile++) {
            int cc = bn + wn * 64 + ntile * 8 + 2 * tg;
            #pragma unroll
            for (int half_ = 0; half_ < 2; half_++) {
                int rr = rr0 + half_ * 8;
                float v0 = acc[mt][ntile][half_ * 2 + 0];
                float v1 = acc[mt][ntile][half_ * 2 + 1];
                size_t idx = (size_t)rr * N_ + cc;
                if (EPI == 0) {
                    *(__half2*)((__half*)Cv + idx) = __floats2half2_rn(v0, v1);
                } else {
                    float2 e = *(const float2*)&extra[idx];
                    *(float2*)((float*)Cv + idx) = make_float2(e.x + v0, e.y + v1);
                }
            }
        }
    }
}

// ---------------- fused SwiGLU FFN-in: f3 = silu(A@w1T^T)*(A@w3T^T) ----------
__global__ __launch_bounds__(256) void gemm_ffn(
    const __half* __restrict__ A, const __half* __restrict__ B1,
    const __half* __restrict__ B3, __half* __restrict__ F3, int K_)
{
    extern __shared__ char smc[];
    uint32_t smb = s2u(smc);
    int tid = threadIdx.x, lane = tid & 31, wid = tid >> 5;
    int wm = wid & 3, wn = wid >> 2;
    int g = lane >> 2, tg = lane & 3;
    int bm = blockIdx.y * 128, bn = blockIdx.x * 64;
    int nt = K_ >> 5;

    int l15 = lane & 15, lk16 = (lane >> 4) * 16;
    int browoff = ((lane >> 4) & 1) * 8 + (lane & 7);
    int bk16 = ((lane >> 3) & 1) * 16;

    float acc[2][2][4][4];
    #pragma unroll
    for (int i = 0; i < 2; i++)
        #pragma unroll
        for (int m = 0; m < 2; m++)
            #pragma unroll
            for (int j = 0; j < 4; j++)
                #pragma unroll
                for (int c = 0; c < 4; c++) acc[i][m][j][c] = 0.0f;

    auto load_stage = [&](int s, int t) {
        int k0 = t * 32;
        uint32_t sa = smb + s * STAGE_BYTES;
        uint32_t sbb = sa + OPB;
        #pragma unroll
        for (int i = 0; i < 2; i++) {
            int e = tid + i * 256;
            int row = e >> 2, ch = e & 3;
            cpa16(sa + row * 80 + ch * 16,
                  A + (size_t)(bm + row) * K_ + k0 + ch * 8);
            const __half* bs = (row < 64)
                ? B1 + (size_t)(bn + row) * K_ + k0 + ch * 8
                : B3 + (size_t)(bn + row - 64) * K_ + k0 + ch * 8;
            cpa16(sbb + row * 80 + ch * 16, bs);
        }
    };

    load_stage(0, 0); asm volatile("cp.async.commit_group;");
    load_stage(1, 1); asm volatile("cp.async.commit_group;");
    load_stage(2, 2); asm volatile("cp.async.commit_group;");

    for (int t = 0; t < nt; t++) {
        if (t + 3 < nt) load_stage((t + 3) & 3, t + 3);
        asm volatile("cp.async.commit_group;");
        asm volatile("cp.async.wait_group 3;");
        __syncthreads();

        uint32_t sA = smb + (t & 3) * STAGE_BYTES;
        uint32_t sB = sA + OPB;
        #pragma unroll
        for (int ks = 0; ks < 2; ks++) {
            uint32_t af[2][4], bf[2][4][2];
            ldm4(af[0], sA + (wm*32      + l15) * 80 + ks*32 + lk16);
            ldm4(af[1], sA + (wm*32 + 16 + l15) * 80 + ks*32 + lk16);
            #pragma unroll
            for (int m = 0; m < 2; m++)
                #pragma unroll
                for (int np = 0; np < 2; np++) {
                    uint32_t d[4];
                    ldm4(d, sB + (m*64 + wn*32 + np*16 + browoff) * 80 + ks*32 + bk16);
                    bf[m][2*np][0] = d[0]; bf[m][2*np][1] = d[1];
                    bf[m][2*np+1][0] = d[2]; bf[m][2*np+1][1] = d[3];
                }
            #pragma unroll
            for (int mt = 0; mt < 2; mt++)
                #pragma unroll
                for (int m = 0; m < 2; m++)
                    #pragma unroll
                    for (int ntile = 0; ntile < 4; ntile++)
                        mma_f16(acc[mt][m][ntile], af[mt], bf[m][ntile]);
        }
        __syncthreads();
    }

    #pragma unroll
    for (int mt = 0; mt < 2; mt++) {
        int rr0 = bm + wm * 32 + mt * 16 + g;
        #pragma unroll
        for (int ntile = 0; ntile < 4; ntile++) {
            int cc = bn + wn * 32 + ntile * 8 + 2 * tg;
            #pragma unroll
            for (int half_ = 0; half_ < 2; half_++) {
                int rr = rr0 + half_ * 8;
                float x10 = acc[mt][0][ntile][half_ * 2 + 0];
                float x11 = acc[mt][0][ntile][half_ * 2 + 1];
                float x30 = acc[mt][1][ntile][half_ * 2 + 0];
                float x31 = acc[mt][1][ntile][half_ * 2 + 1];
                float f0 = x10 / (1.0f + __expf(-x10)) * x30;
                float f1 = x11 / (1.0f + __expf(-x11)) * x31;
                *(__half2*)&F3[(size_t)rr * DFF + cc] = __floats2half2_rn(f0, f1);
            }
        }
    }
}

// ---------------- fp16 MMA flash attention (causal), paired Q tiles ----------
// grid (8, NH, BB); block handles q-tiles {bx, 15-bx}; balanced single wave.
// Per KV tile, softmax/PV are split into two 32-col chunks so scalar softmax
// of one chunk overlaps in-flight HMMAs of the other (S_B / PV_A).
#define ASTR 72                      // halves; row stride 144 bytes
#define ASMEM ((128 + 4*64)*ASTR*2)  // 55296 bytes
__global__ __launch_bounds__(256) void attn_mma(const __half* __restrict__ qkv,
                                                __half* __restrict__ o) {
    extern __shared__ __half sma[];
    __half* Qs = sma;                         // 128 x ASTR
    __half* K0 = Qs + 128 * ASTR;             // 2 x (64 x ASTR)
    __half* V0 = K0 + 2 * 64 * ASTR;

    int h = blockIdx.y, b = blockIdx.z;
    int tid = threadIdx.x, lane = tid & 31, wid = tid >> 5;
    int g = lane >> 2, tg = lane & 3;
    const float scale = 0.125f;

    const __half* qb = qkv + (size_t)b * SS * QKVS + h * DH;
    const __half* kb = qb + DM;
    const __half* vb = qb + 2 * DM;

    uint32_t sQ = s2u(Qs);
    uint32_t ksb[2] = { s2u(K0), s2u(K0 + 64 * ASTR) };
    uint32_t vsb[2] = { s2u(V0), s2u(V0 + 64 * ASTR) };

    int rb = wid * 16;
    int l15 = lane & 15, lk16 = (lane >> 4) * 16;
    int browoff = ((lane >> 4) & 1) * 8 + (lane & 7);
    int bk16 = ((lane >> 3) & 1) * 16;
    int vrowoff = ((lane >> 3) & 1) * 8 + (lane & 7);
    int vcol16 = (lane >> 4) * 16;

    #pragma unroll 1
    for (int pass = 0; pass < 2; pass++) {
        int qt = pass ? (15 - blockIdx.x) : blockIdx.x;

        // load Q tile (128 x 64 halves)
        #pragma unroll
        for (int i = 0; i < 4; i++) {
            int e = tid + i * 256;
            int r = e >> 3, c8 = (e & 7) * 8;
            *(uint4*)&Qs[r * ASTR + c8] =
                *(const uint4*)&qb[(size_t)(qt * 128 + r) * QKVS + c8];
        }

        auto issueKV = [&](int kt) {
            int bf_ = kt & 1;
            #pragma unroll
            for (int i = 0; i < 2; i++) {
                int e = tid + i * 256;
                int r = e >> 3, c8 = (e & 7) * 8;
                size_t gidx = (size_t)(kt * 64 + r) * QKVS + c8;
                cpa16(ksb[bf_] + r * 144 + c8 * 2, kb + gidx);
                cpa16(vsb[bf_] + r * 144 + c8 * 2, vb + gidx);
            }
        };
        issueKV(0);
        asm volatile("cp.async.commit_group;");

        float oacc[8][4];
        #pragma unroll
        for (int i = 0; i < 8; i++)
            #pragma unroll
            for (int c = 0; c < 4; c++) oacc[i][c] = 0.0f;
        float mrow[2] = {-1e30f, -1e30f};
        float lrow[2] = {0.0f, 0.0f};

        int rowbase = qt * 128 + rb;
        int kmax = 2 * qt + 1;
        for (int kt = 0; kt <= kmax; kt++) {
            if (kt < kmax) issueKV(kt + 1);
            asm volatile("cp.async.commit_group;");
            asm volatile("cp.async.wait_group 1;");
            __syncthreads();

            if (kt * 64 <= rowbase + 15) {
                uint32_t sK = ksb[kt & 1], sV = vsb[kt & 1];
                int row0 = rowbase + g, row1 = row0 + 8;
                bool needmask = (kt * 64 + 63) > rowbase;

                float sacc[8][4];
                #pragma unroll
                for (int i = 0; i < 8; i++)
                    #pragma unroll
                    for (int c = 0; c < 4; c++) sacc[i][c] = 0.0f;

                // S chunk A (cols 0..31), then chunk B (cols 32..63)
                #pragma unroll
                for (int ch = 0; ch < 2; ch++) {
                    #pragma unroll
                    for (int kk = 0; kk < 4; kk++) {
                        uint32_t af[4];
                        ldm4(af, sQ + (rb + l15) * 144 + kk * 32 + lk16);
                        #pragma unroll
                        for (int np = 0; np < 2; np++) {
                            int npa = ch * 2 + np;
                            uint32_t d[4];
                            ldm4(d, sK + (npa * 16 + browoff) * 144 + kk * 32 + bk16);
                            uint32_t b0[2] = { d[0], d[1] }, b1[2] = { d[2], d[3] };
                            mma_f16(sacc[2*npa],   af, b0);
                            mma_f16(sacc[2*npa+1], af, b1);
                        }
                    }
                }

                // two chunked online-softmax + PV phases; scalar work of each
                // chunk overlaps the other chunk's in-flight HMMAs
                #pragma unroll
                for (int ch = 0; ch < 2; ch++) {
                    float* sc = &sacc[ch * 4][0];    // 4 n-tiles of this chunk
                    int colbase = kt * 64 + ch * 32;

                    // scale + mask
                    #pragma unroll
                    for (int nt = 0; nt < 4; nt++) {
                        float* s4 = sc + nt * 4;
                        int c0 = colbase + nt * 8 + 2 * tg, c1 = c0 + 1;
                        s4[0] *= scale; s4[1] *= scale;
                        s4[2] *= scale; s4[3] *= scale;
                        if (needmask) {
                            if (c0 > row0) s4[0] = -1e30f;
                            if (c1 > row0) s4[1] = -1e30f;
                            if (c0 > row1) s4[2] = -1e30f;
                            if (c1 > row1) s4[3] = -1e30f;
                        }
                    }

                    float rmax0 = -1e30f, rmax1 = -1e30f;
                    #pragma unroll
                    for (int nt = 0; nt < 4; nt++) {
                        float* s4 = sc + nt * 4;
                        rmax0 = fmaxf(rmax0, fmaxf(s4[0], s4[1]));
                        rmax1 = fmaxf(rmax1, fmaxf(s4[2], s4[3]));
                    }
                    rmax0 = fmaxf(rmax0, __shfl_xor_sync(0xffffffffu, rmax0, 1));
                    rmax0 = fmaxf(rmax0, __shfl_xor_sync(0xffffffffu, rmax0, 2));
                    rmax1 = fmaxf(rmax1, __shfl_xor_sync(0xffffffffu, rmax1, 1));
                    rmax1 = fmaxf(rmax1, __shfl_xor_sync(0xffffffffu, rmax1, 2));

                    float m0 = fmaxf(mrow[0], rmax0), m1 = fmaxf(mrow[1], rmax1);
                    float r0 = __expf(mrow[0] - m0), r1 = __expf(mrow[1] - m1);
                    mrow[0] = m0; mrow[1] = m1;

                    uint32_t plo[4], phi[4];
                    float sum0 = 0.0f, sum1 = 0.0f;
                    #pragma unroll
                    for (int nt = 0; nt < 4; nt++) {
                        float* s4 = sc + nt * 4;
                        float p0 = __expf(s4[0] - m0);
                        float p1 = __expf(s4[1] - m0);
                        float p2 = __expf(s4[2] - m1);
                        float p3 = __expf(s4[3] - m1);
                        sum0 += p0 + p1; sum1 += p2 + p3;
                        plo[nt] = h2u(p0, p1);
                        phi[nt] = h2u(p2, p3);
                    }
                    sum0 += __shfl_xor_sync(0xffffffffu, sum0, 1);
                    sum0 += __shfl_xor_sync(0xffffffffu, sum0, 2);
                    sum1 += __shfl_xor_sync(0xffffffffu, sum1, 1);
                    sum1 += __shfl_xor_sync(0xffffffffu, sum1, 2);
                    lrow[0] = lrow[0] * r0 + sum0;
                    lrow[1] = lrow[1] * r1 + sum1;

                    #pragma unroll
                    for (int dt = 0; dt < 8; dt++) {
                        oacc[dt][0] *= r0; oacc[dt][1] *= r0;
                        oacc[dt][2] *= r1; oacc[dt][3] *= r1;
                    }

                    // PV for this chunk: V rows ch*32 .. ch*32+31
                    #pragma unroll
                    for (int kk2 = 0; kk2 < 2; kk2++) {
                        int kv = ch * 2 + kk2;
                        uint32_t af[4] = { plo[2*kk2], phi[2*kk2],
                                           plo[2*kk2+1], phi[2*kk2+1] };
                        #pragma unroll
                        for (int dp = 0; dp < 4; dp++) {
                            uint32_t d[4];
                            ldm4t(d, sV + (kv * 16 + vrowoff) * 144 + dp * 32 + vcol16);
                            uint32_t b0[2] = { d[0], d[1] }, b1[2] = { d[2], d[3] };
                            mma_f16(oacc[2*dp],   af, b0);
                            mma_f16(oacc[2*dp+1], af, b1);
                        }
                    }
                }
            }
            __syncthreads();
        }

        float inv0 = 1.0f / lrow[0], inv1 = 1.0f / lrow[1];
        size_t orow0 = (size_t)b * SS + qt * 128 + rb + g;
        #pragma unroll
        for (int dt = 0; dt < 8; dt++) {
            int d = h * DH + dt * 8 + 2 * tg;
            *(__half2*)&o[orow0 * DM + d] =
                __floats2half2_rn(oacc[dt][0] * inv0, oacc[dt][1] * inv0);
            *(__half2*)&o[(orow0 + 8) * DM + d] =
                __floats2half2_rn(oacc[dt][2] * inv1, oacc[dt][3] * inv1);
        }
        __syncthreads();   // Q/K/V smem safe to overwrite in next pass
    }
}

// ---------------- launch ------------------------------------------------------
extern "C" void kernel_launch(void* const* d_in, const int* in_sizes, int n_in,
                              void* d_out, int out_size) {
    const float* x   = (const float*)d_in[0];
    const float* g1  = (const float*)d_in[1];
    const float* g2  = (const float*)d_in[2];
    const float* w_q = (const float*)d_in[3];
    const float* w_k = (const float*)d_in[4];
    const float* w_v = (const float*)d_in[5];
    const float* w_o = (const float*)d_in[6];
    const float* w1  = (const float*)d_in[7];
    const float* w2  = (const float*)d_in[8];
    const float* w3  = (const float*)d_in[9];
    float* out = (float*)d_out;

    __half *xn, *qkv, *ap, *hn, *f3, *wqkvT, *woT, *w1T, *w3T, *w2T;
    float *hres;
    cudaGetSymbolAddress((void**)&xn,    g_xn);
    cudaGetSymbolAddress((void**)&qkv,   g_qkv);
    cudaGetSymbolAddress((void**)&ap,    g_attn);
    cudaGetSymbolAddress((void**)&hres,  g_hres);
    cudaGetSymbolAddress((void**)&hn,    g_hn);
    cudaGetSymbolAddress((void**)&f3,    g_f3);
    cudaGetSymbolAddress((void**)&wqkvT, g_wqkvT);
    cudaGetSymbolAddress((void**)&woT,   g_woT);
    cudaGetSymbolAddress((void**)&w1T,   g_w1T);
    cudaGetSymbolAddress((void**)&w3T,   g_w3T);
    cudaGetSymbolAddress((void**)&w2T,   g_w2T);

    cudaFuncSetAttribute(gemm_mma<0>, cudaFuncAttributeMaxDynamicSharedMemorySize, GSMEM);
    cudaFuncSetAttribute(gemm_mma<1>, cudaFuncAttributeMaxDynamicSharedMemorySize, GSMEM);
    cudaFuncSetAttribute(gemm_ffn, cudaFuncAttributeMaxDynamicSharedMemorySize, GSMEM);
    cudaFuncSetAttribute(attn_mma, cudaFuncAttributeMaxDynamicSharedMemorySize, ASMEM);

    // merged weight transpose: all 7 weights in one launch
    TransAll ja;
    const float* srcs[7] = { w_q, w_k, w_v, w_o, w1, w3, w2 };
    __half* dsts[7] = { wqkvT, wqkvT + DM*DM, wqkvT + 2*DM*DM, woT, w1T, w3T, w2T };
    int Rs[7] = { DM, DM, DM, DM, DM, DM, DFF };
    int Cs[7] = { DM, DM, DM, DM, DFF, DFF, DM };
    int cum = 0;
    for (int i = 0; i < 7; i++) {
        ja.src[i] = srcs[i]; ja.dst[i] = dsts[i];
        ja.R[i] = Rs[i]; ja.C[i] = Cs[i];
        ja.start[i] = cum;
        cum += (Rs[i] / 32) * (Cs[i] / 32);
    }
    ja.start[7] = cum;
    transpose_all_k<<<cum, 256>>>(ja);

    dim3 gQKV(QKVS / 128, MM / 128);               // (24, 32)
    dim3 gD(DM / 128, MM / 128);                   // (8, 32)
    dim3 gFF(DFF / 64, MM / 128);                  // (43, 32)

    // 1. norm1 -> fp16
    rmsnorm_h<<<MM, 256>>>(x, g1, xn);
    // 2. fused qkv projection -> fp16
    gemm_mma<0><<<gQKV, 256, GSMEM>>>(xn, wqkvT, nullptr, qkv, MM, QKVS, DM);
    // 3. causal flash attention -> fp16 (paired Q tiles, chunked softmax/PV)
    attn_mma<<<dim3(8, NH, BB), 256, ASMEM>>>(qkv, ap);
    // 4. h_res = x + attn @ w_o  (fp32)
    gemm_mma<1><<<gD, 256, GSMEM>>>(ap, woT, x, hres, MM, DM, DM);
    // 5. norm2 -> fp16
    rmsnorm_h<<<MM, 256>>>(hres, g2, hn);
    // 6+7. fused f3 = silu(hn @ w1) * (hn @ w3) -> fp16
    gemm_ffn<<<gFF, 256, GSMEM>>>(hn, w1T, w3T, f3, DM);
    // 8. out = h_res + f3 @ w2  (fp32)
    gemm_mma<1><<<gD, 256, GSMEM>>>(f3, w2T, hres, out, MM, DM, DFF);
}

// round 17
// speedup vs baseline: 1.0119x; 1.0119x over previous
#include <cuda_runtime.h>
#include <cuda_fp16.h>
#include <math.h>
#include <stdint.h>
#include <string.h>

// Problem constants
#define BB 2
#define SS 2048
#define DM 1024
#define NH 16
#define DH 64
#define DFF 2752
#define MM (BB*SS)          // 4096 rows
#define EPSV 1e-5f
#define QKVS (3*DM)

// ---------------- scratch (static __device__, no allocation) ----------------
__device__ __align__(16) __half g_xn  [MM*DM];
__device__ __align__(16) __half g_qkv [MM*QKVS];
__device__ __align__(16) __half g_attn[MM*DM];
__device__ float  g_hres[MM*DM];
__device__ __align__(16) __half g_hn  [MM*DM];
__device__ __align__(16) __half g_f3  [MM*DFF];
// transposed fp16 weights, [N,K] row-major
__device__ __align__(16) __half g_wqkvT[3*DM*DM];
__device__ __align__(16) __half g_woT[DM*DM];
__device__ __align__(16) __half g_w1T[DFF*DM];
__device__ __align__(16) __half g_w3T[DFF*DM];
__device__ __align__(16) __half g_w2T[DM*DFF];

// ---------------- helpers ----------------------------------------------------
__device__ __forceinline__ uint32_t s2u(const void* p) {
    uint32_t a;
    asm("{ .reg .u64 t; cvta.to.shared.u64 t, %1; cvt.u32.u64 %0, t; }"
        : "=r"(a) : "l"(p));
    return a;
}
__device__ __forceinline__ void cpa16(uint32_t dst, const void* src) {
    asm volatile("cp.async.cg.shared.global [%0], [%1], 16;"
                 :: "r"(dst), "l"(src) : "memory");
}
__device__ __forceinline__ void mma_f16(float* c, const uint32_t* a, const uint32_t* b) {
    asm volatile("mma.sync.aligned.m16n8k16.row.col.f32.f16.f16.f32 "
        "{%0,%1,%2,%3}, {%4,%5,%6,%7}, {%8,%9}, {%0,%1,%2,%3};"
        : "+f"(c[0]), "+f"(c[1]), "+f"(c[2]), "+f"(c[3])
        : "r"(a[0]), "r"(a[1]), "r"(a[2]), "r"(a[3]), "r"(b[0]), "r"(b[1]));
}
__device__ __forceinline__ void ldm4(uint32_t* d, uint32_t addr) {
    asm volatile("ldmatrix.sync.aligned.m8n8.x4.shared.b16 {%0,%1,%2,%3}, [%4];"
        : "=r"(d[0]), "=r"(d[1]), "=r"(d[2]), "=r"(d[3]) : "r"(addr));
}
__device__ __forceinline__ void ldm4t(uint32_t* d, uint32_t addr) {
    asm volatile("ldmatrix.sync.aligned.m8n8.x4.trans.shared.b16 {%0,%1,%2,%3}, [%4];"
        : "=r"(d[0]), "=r"(d[1]), "=r"(d[2]), "=r"(d[3]) : "r"(addr));
}
__device__ __forceinline__ uint32_t h2u(float lo, float hi) {
    uint32_t r;
    asm("cvt.rn.f16x2.f32 %0, %1, %2;" : "=r"(r) : "f"(hi), "f"(lo));
    return r;
}

// ---------------- RMSNorm (fp32 in -> fp16 out) ------------------------------
__global__ __launch_bounds__(256) void rmsnorm_h(const float* __restrict__ x,
                                                 const float* __restrict__ g,
                                                 __half* __restrict__ out) {
    int row = blockIdx.x;
    const float* xr = x + (size_t)row * DM;
    __half* orow = out + (size_t)row * DM;
    int t = threadIdx.x;
    float4 v = *(const float4*)&xr[t * 4];
    float ss = v.x*v.x + v.y*v.y + v.z*v.z + v.w*v.w;
    for (int o = 16; o > 0; o >>= 1) ss += __shfl_xor_sync(0xffffffffu, ss, o);
    __shared__ float wsum[8];
    if ((t & 31) == 0) wsum[t >> 5] = ss;
    __syncthreads();
    if (t < 8) {
        float s = wsum[t];
        for (int o = 4; o > 0; o >>= 1) s += __shfl_xor_sync(0xffu, s, o);
        if (t == 0) wsum[0] = s;
    }
    __syncthreads();
    float inv = rsqrtf(wsum[0] * (1.0f / DM) + EPSV);
    float4 gv = *(const float4*)&g[t * 4];
    ((__half2*)orow)[t*2  ] = __floats2half2_rn(v.x*inv*gv.x, v.y*inv*gv.y);
    ((__half2*)orow)[t*2+1] = __floats2half2_rn(v.z*inv*gv.z, v.w*inv*gv.w);
}

// ---------------- merged weight transpose fp32 -> fp16 [N,K], one launch -----
struct TransAll {
    const float* src[7];
    __half* dst[7];
    int R[7], C[7];
    int start[8];
};
__global__ __launch_bounds__(256) void transpose_all_k(TransAll ja) {
    __shared__ float t[32][33];
    int tile = blockIdx.x;
    int w = 0;
    while (tile >= ja.start[w + 1]) w++;
    int local = tile - ja.start[w];
    const float* in = ja.src[w];
    __half* out = ja.dst[w];
    int R = ja.R[w], C = ja.C[w];
    int tilesX = C >> 5;
    int bx = (local % tilesX) * 32, by = (local / tilesX) * 32;
    int tx = threadIdx.x & 31, ty = threadIdx.x >> 5;
    #pragma unroll
    for (int i = 0; i < 32; i += 8)
        t[ty + i][tx] = in[(size_t)(by + ty + i) * C + bx + tx];
    __syncthreads();
    #pragma unroll
    for (int i = 0; i < 32; i += 8)
        out[(size_t)(bx + ty + i) * R + by + tx] = __float2half(t[tx][ty + i]);
}

// ---------------- fp16 mma.sync GEMM (ldmatrix) ------------------------------
// C[M,N] = A[M,K] @ Wt[N,K]^T.  BM=BN=128, BK=32, 4-stage cp.async.
// EPI: 0 plain->half, 1 residual(+extra)->float
#define BKH 40
#define OPB (128*BKH*2)
#define STAGE_BYTES (2u*OPB)
#define GSMEM (4u*STAGE_BYTES)       // 81920

template <int EPI>
__global__ __launch_bounds__(256) void gemm_mma(
    const __half* __restrict__ A, const __half* __restrict__ Bw,
    const float* __restrict__ extra, void* __restrict__ Cv,
    int M_, int N_, int K_)
{
    extern __shared__ char smc[];
    uint32_t smb = s2u(smc);
    int tid = threadIdx.x, lane = tid & 31, wid = tid >> 5;
    int wm = wid & 3, wn = wid >> 2;
    int g = lane >> 2, tg = lane & 3;
    int bm = blockIdx.y * 128, bn = blockIdx.x * 128;
    int nt = K_ >> 5;

    int l15 = lane & 15, lk16 = (lane >> 4) * 16;
    int browoff = ((lane >> 4) & 1) * 8 + (lane & 7);
    int bk16 = ((lane >> 3) & 1) * 16;

    float acc[2][8][4];
    #pragma unroll
    for (int i = 0; i < 2; i++)
        #pragma unroll
        for (int j = 0; j < 8; j++)
            #pragma unroll
            for (int c = 0; c < 4; c++) acc[i][j][c] = 0.0f;

    auto load_stage = [&](int s, int t) {
        int k0 = t * 32;
        uint32_t sa = smb + s * STAGE_BYTES;
        uint32_t sbb = sa + OPB;
        #pragma unroll
        for (int i = 0; i < 2; i++) {
            int e = tid + i * 256;
            int row = e >> 2, ch = e & 3;
            cpa16(sa + row * 80 + ch * 16,
                  A + (size_t)(bm + row) * K_ + k0 + ch * 8);
            cpa16(sbb + row * 80 + ch * 16,
                  Bw + (size_t)(bn + row) * K_ + k0 + ch * 8);
        }
    };

    load_stage(0, 0); asm volatile("cp.async.commit_group;");
    if (nt > 1) load_stage(1, 1); asm volatile("cp.async.commit_group;");
    if (nt > 2) load_stage(2, 2); asm volatile("cp.async.commit_group;");

    for (int t = 0; t < nt; t++) {
        if (t + 3 < nt) load_stage((t + 3) & 3, t + 3);
        asm volatile("cp.async.commit_group;");
        asm volatile("cp.async.wait_group 3;");
        __syncthreads();

        uint32_t sA = smb + (t & 3) * STAGE_BYTES;
        uint32_t sB = sA + OPB;
        #pragma unroll
        for (int ks = 0; ks < 2; ks++) {
            uint32_t af[2][4], bf[8][2];
            ldm4(af[0], sA + (wm*32      + l15) * 80 + ks*32 + lk16);
            ldm4(af[1], sA + (wm*32 + 16 + l15) * 80 + ks*32 + lk16);
            #pragma unroll
            for (int np = 0; np < 4; np++) {
                uint32_t d[4];
                ldm4(d, sB + (wn*64 + np*16 + browoff) * 80 + ks*32 + bk16);
                bf[2*np][0] = d[0]; bf[2*np][1] = d[1];
                bf[2*np+1][0] = d[2]; bf[2*np+1][1] = d[3];
            }
            #pragma unroll
            for (int mt = 0; mt < 2; mt++)
                #pragma unroll
                for (int ntile = 0; ntile < 8; ntile++)
                    mma_f16(acc[mt][ntile], af[mt], bf[ntile]);
        }
        __syncthreads();
    }

    #pragma unroll
    for (int mt = 0; mt < 2; mt++) {
        int rr0 = bm + wm * 32 + mt * 16 + g;
        #pragma unroll
        for (int ntile = 0; ntile < 8; ntile++) {
            int cc = bn + wn * 64 + ntile * 8 + 2 * tg;
            #pragma unroll
            for (int half_ = 0; half_ < 2; half_++) {
                int rr = rr0 + half_ * 8;
                float v0 = acc[mt][ntile][half_ * 2 + 0];
                float v1 = acc[mt][ntile][half_ * 2 + 1];
                size_t idx = (size_t)rr * N_ + cc;
                if (EPI == 0) {
                    *(__half2*)((__half*)Cv + idx) = __floats2half2_rn(v0, v1);
                } else {
                    float2 e = *(const float2*)&extra[idx];
                    *(float2*)((float*)Cv + idx) = make_float2(e.x + v0, e.y + v1);
                }
            }
        }
    }
}

// ---------------- fused SwiGLU FFN-in: f3 = silu(A@w1T^T)*(A@w3T^T) ----------
__global__ __launch_bounds__(256) void gemm_ffn(
    const __half* __restrict__ A, const __half* __restrict__ B1,
    const __half* __restrict__ B3, __half* __restrict__ F3, int K_)
{
    extern __shared__ char smc[];
    uint32_t smb = s2u(smc);
    int tid = threadIdx.x, lane = tid & 31, wid = tid >> 5;
    int wm = wid & 3, wn = wid >> 2;
    int g = lane >> 2, tg = lane & 3;
    int bm = blockIdx.y * 128, bn = blockIdx.x * 64;
    int nt = K_ >> 5;

    int l15 = lane & 15, lk16 = (lane >> 4) * 16;
    int browoff = ((lane >> 4) & 1) * 8 + (lane & 7);
    int bk16 = ((lane >> 3) & 1) * 16;

    float acc[2][2][4][4];
    #pragma unroll
    for (int i = 0; i < 2; i++)
        #pragma unroll
        for (int m = 0; m < 2; m++)
            #pragma unroll
            for (int j = 0; j < 4; j++)
                #pragma unroll
                for (int c = 0; c < 4; c++) acc[i][m][j][c] = 0.0f;

    auto load_stage = [&](int s, int t) {
        int k0 = t * 32;
        uint32_t sa = smb + s * STAGE_BYTES;
        uint32_t sbb = sa + OPB;
        #pragma unroll
        for (int i = 0; i < 2; i++) {
            int e = tid + i * 256;
            int row = e >> 2, ch = e & 3;
            cpa16(sa + row * 80 + ch * 16,
                  A + (size_t)(bm + row) * K_ + k0 + ch * 8);
            const __half* bs = (row < 64)
                ? B1 + (size_t)(bn + row) * K_ + k0 + ch * 8
                : B3 + (size_t)(bn + row - 64) * K_ + k0 + ch * 8;
            cpa16(sbb + row * 80 + ch * 16, bs);
        }
    };

    load_stage(0, 0); asm volatile("cp.async.commit_group;");
    load_stage(1, 1); asm volatile("cp.async.commit_group;");
    load_stage(2, 2); asm volatile("cp.async.commit_group;");

    for (int t = 0; t < nt; t++) {
        if (t + 3 < nt) load_stage((t + 3) & 3, t + 3);
        asm volatile("cp.async.commit_group;");
        asm volatile("cp.async.wait_group 3;");
        __syncthreads();

        uint32_t sA = smb + (t & 3) * STAGE_BYTES;
        uint32_t sB = sA + OPB;
        #pragma unroll
        for (int ks = 0; ks < 2; ks++) {
            uint32_t af[2][4], bf[2][4][2];
            ldm4(af[0], sA + (wm*32      + l15) * 80 + ks*32 + lk16);
            ldm4(af[1], sA + (wm*32 + 16 + l15) * 80 + ks*32 + lk16);
            #pragma unroll
            for (int m = 0; m < 2; m++)
                #pragma unroll
                for (int np = 0; np < 2; np++) {
                    uint32_t d[4];
                    ldm4(d, sB + (m*64 + wn*32 + np*16 + browoff) * 80 + ks*32 + bk16);
                    bf[m][2*np][0] = d[0]; bf[m][2*np][1] = d[1];
                    bf[m][2*np+1][0] = d[2]; bf[m][2*np+1][1] = d[3];
                }
            #pragma unroll
            for (int mt = 0; mt < 2; mt++)
                #pragma unroll
                for (int m = 0; m < 2; m++)
                    #pragma unroll
                    for (int ntile = 0; ntile < 4; ntile++)
                        mma_f16(acc[mt][m][ntile], af[mt], bf[m][ntile]);
        }
        __syncthreads();
    }

    #pragma unroll
    for (int mt = 0; mt < 2; mt++) {
        int rr0 = bm + wm * 32 + mt * 16 + g;
        #pragma unroll
        for (int ntile = 0; ntile < 4; ntile++) {
            int cc = bn + wn * 32 + ntile * 8 + 2 * tg;
            #pragma unroll
            for (int half_ = 0; half_ < 2; half_++) {
                int rr = rr0 + half_ * 8;
                float x10 = acc[mt][0][ntile][half_ * 2 + 0];
                float x11 = acc[mt][0][ntile][half_ * 2 + 1];
                float x30 = acc[mt][1][ntile][half_ * 2 + 0];
                float x31 = acc[mt][1][ntile][half_ * 2 + 1];
                float f0 = x10 / (1.0f + __expf(-x10)) * x30;
                float f1 = x11 / (1.0f + __expf(-x11)) * x31;
                *(__half2*)&F3[(size_t)rr * DFF + cc] = __floats2half2_rn(f0, f1);
            }
        }
    }
}

// ---------------- fp16 MMA flash attention (causal), paired Q tiles ----------
// grid (8, NH, BB); block handles q-tiles {bx, 15-bx}; balanced single wave.
// One barrier per KV tile: wait_group 0 -> sync -> prefetch next -> compute.
// Softmax in exp2 domain (scale*log2e folded into one multiply).
#define ASTR 72                      // halves; row stride 144 bytes
#define ASMEM ((128 + 4*64)*ASTR*2)  // 55296 bytes
__global__ __launch_bounds__(256) void attn_mma(const __half* __restrict__ qkv,
                                                __half* __restrict__ o) {
    extern __shared__ __half sma[];
    __half* Qs = sma;                         // 128 x ASTR
    __half* K0 = Qs + 128 * ASTR;             // 2 x (64 x ASTR)
    __half* V0 = K0 + 2 * 64 * ASTR;

    int h = blockIdx.y, b = blockIdx.z;
    int tid = threadIdx.x, lane = tid & 31, wid = tid >> 5;
    int g = lane >> 2, tg = lane & 3;
    const float sc2 = 0.125f * 1.4426950408889634f;   // scale * log2(e)

    const __half* qb = qkv + (size_t)b * SS * QKVS + h * DH;
    const __half* kb = qb + DM;
    const __half* vb = qb + 2 * DM;

    uint32_t sQ = s2u(Qs);
    uint32_t ksb[2] = { s2u(K0), s2u(K0 + 64 * ASTR) };
    uint32_t vsb[2] = { s2u(V0), s2u(V0 + 64 * ASTR) };

    int rb = wid * 16;
    int l15 = lane & 15, lk16 = (lane >> 4) * 16;
    int browoff = ((lane >> 4) & 1) * 8 + (lane & 7);
    int bk16 = ((lane >> 3) & 1) * 16;
    int vrowoff = ((lane >> 3) & 1) * 8 + (lane & 7);
    int vcol16 = (lane >> 4) * 16;

    #pragma unroll 1
    for (int pass = 0; pass < 2; pass++) {
        int qt = pass ? (15 - blockIdx.x) : blockIdx.x;

        // load Q tile (128 x 64 halves)
        #pragma unroll
        for (int i = 0; i < 4; i++) {
            int e = tid + i * 256;
            int r = e >> 3, c8 = (e & 7) * 8;
            *(uint4*)&Qs[r * ASTR + c8] =
                *(const uint4*)&qb[(size_t)(qt * 128 + r) * QKVS + c8];
        }

        auto issueKV = [&](int kt) {
            int bf_ = kt & 1;
            #pragma unroll
            for (int i = 0; i < 2; i++) {
                int e = tid + i * 256;
                int r = e >> 3, c8 = (e & 7) * 8;
                size_t gidx = (size_t)(kt * 64 + r) * QKVS + c8;
                cpa16(ksb[bf_] + r * 144 + c8 * 2, kb + gidx);
                cpa16(vsb[bf_] + r * 144 + c8 * 2, vb + gidx);
            }
        };
        issueKV(0);
        asm volatile("cp.async.commit_group;");

        float oacc[8][4];
        #pragma unroll
        for (int i = 0; i < 8; i++)
            #pragma unroll
            for (int c = 0; c < 4; c++) oacc[i][c] = 0.0f;
        float mrow[2] = {-1e30f, -1e30f};      // log2-domain running max
        float lrow[2] = {0.0f, 0.0f};

        int rowbase = qt * 128 + rb;
        int kmax = 2 * qt + 1;
        for (int kt = 0; kt <= kmax; kt++) {
            // KV kt is the newest committed group; wait for it, then one barrier.
            asm volatile("cp.async.wait_group 0;");
            __syncthreads();
            // prefetch next tile into the buffer last read at iter kt-1
            // (safe: all warps passed the barrier after finishing kt-1)
            if (kt < kmax) {
                issueKV(kt + 1);
                asm volatile("cp.async.commit_group;");
            }

            if (kt * 64 <= rowbase + 15) {
                uint32_t sK = ksb[kt & 1], sV = vsb[kt & 1];

                // S = Q K^T
                float sacc[8][4];
                #pragma unroll
                for (int i = 0; i < 8; i++)
                    #pragma unroll
                    for (int c = 0; c < 4; c++) sacc[i][c] = 0.0f;
                #pragma unroll
                for (int kk = 0; kk < 4; kk++) {
                    uint32_t af[4];
                    ldm4(af, sQ + (rb + l15) * 144 + kk * 32 + lk16);
                    #pragma unroll
                    for (int np = 0; np < 4; np++) {
                        uint32_t d[4];
                        ldm4(d, sK + (np * 16 + browoff) * 144 + kk * 32 + bk16);
                        uint32_t b0[2] = { d[0], d[1] }, b1[2] = { d[2], d[3] };
                        mma_f16(sacc[2*np],   af, b0);
                        mma_f16(sacc[2*np+1], af, b1);
                    }
                }

                // scale (log2 domain) + causal mask
                int row0 = rowbase + g, row1 = row0 + 8;
                bool needmask = (kt * 64 + 63) > rowbase;
                #pragma unroll
                for (int nt = 0; nt < 8; nt++) {
                    int c0 = kt * 64 + nt * 8 + 2 * tg, c1 = c0 + 1;
                    sacc[nt][0] *= sc2; sacc[nt][1] *= sc2;
                    sacc[nt][2] *= sc2; sacc[nt][3] *= sc2;
                    if (needmask) {
                        if (c0 > row0) sacc[nt][0] = -1e30f;
                        if (c1 > row0) sacc[nt][1] = -1e30f;
                        if (c0 > row1) sacc[nt][2] = -1e30f;
                        if (c1 > row1) sacc[nt][3] = -1e30f;
                    }
                }

                // online softmax (exp2 domain)
                float rmax0 = -1e30f, rmax1 = -1e30f;
                #pragma unroll
                for (int nt = 0; nt < 8; nt++) {
                    rmax0 = fmaxf(rmax0, fmaxf(sacc[nt][0], sacc[nt][1]));
                    rmax1 = fmaxf(rmax1, fmaxf(sacc[nt][2], sacc[nt][3]));
                }
                rmax0 = fmaxf(rmax0, __shfl_xor_sync(0xffffffffu, rmax0, 1));
                rmax0 = fmaxf(rmax0, __shfl_xor_sync(0xffffffffu, rmax0, 2));
                rmax1 = fmaxf(rmax1, __shfl_xor_sync(0xffffffffu, rmax1, 1));
                rmax1 = fmaxf(rmax1, __shfl_xor_sync(0xffffffffu, rmax1, 2));

                float m0 = fmaxf(mrow[0], rmax0), m1 = fmaxf(mrow[1], rmax1);
                float r0 = exp2f(mrow[0] - m0), r1 = exp2f(mrow[1] - m1);
                mrow[0] = m0; mrow[1] = m1;

                uint32_t plo[8], phi[8];
                float sum0 = 0.0f, sum1 = 0.0f;
                #pragma unroll
                for (int nt = 0; nt < 8; nt++) {
                    float p0 = exp2f(sacc[nt][0] - m0);
                    float p1 = exp2f(sacc[nt][1] - m0);
                    float p2 = exp2f(sacc[nt][2] - m1);
                    float p3 = exp2f(sacc[nt][3] - m1);
                    sum0 += p0 + p1; sum1 += p2 + p3;
                    plo[nt] = h2u(p0, p1);
                    phi[nt] = h2u(p2, p3);
                }
                sum0 += __shfl_xor_sync(0xffffffffu, sum0, 1);
                sum0 += __shfl_xor_sync(0xffffffffu, sum0, 2);
                sum1 += __shfl_xor_sync(0xffffffffu, sum1, 1);
                sum1 += __shfl_xor_sync(0xffffffffu, sum1, 2);
                lrow[0] = lrow[0] * r0 + sum0;
                lrow[1] = lrow[1] * r1 + sum1;

                #pragma unroll
                for (int dt = 0; dt < 8; dt++) {
                    oacc[dt][0] *= r0; oacc[dt][1] *= r0;
                    oacc[dt][2] *= r1; oacc[dt][3] *= r1;
                }

                // O += P @ V
                #pragma unroll
                for (int kk = 0; kk < 4; kk++) {
                    uint32_t af[4] = { plo[2*kk], phi[2*kk], plo[2*kk+1], phi[2*kk+1] };
                    #pragma unroll
                    for (int dp = 0; dp < 4; dp++) {
                        uint32_t d[4];
                        ldm4t(d, sV + (kk * 16 + vrowoff) * 144 + dp * 32 + vcol16);
                        uint32_t b0[2] = { d[0], d[1] }, b1[2] = { d[2], d[3] };
                        mma_f16(oacc[2*dp],   af, b0);
                        mma_f16(oacc[2*dp+1], af, b1);
                    }
                }
            }
        }

        float inv0 = 1.0f / lrow[0], inv1 = 1.0f / lrow[1];
        size_t orow0 = (size_t)b * SS + qt * 128 + rb + g;
        #pragma unroll
        for (int dt = 0; dt < 8; dt++) {
            int d = h * DH + dt * 8 + 2 * tg;
            *(__half2*)&o[orow0 * DM + d] =
                __floats2half2_rn(oacc[dt][0] * inv0, oacc[dt][1] * inv0);
            *(__half2*)&o[(orow0 + 8) * DM + d] =
                __floats2half2_rn(oacc[dt][2] * inv1, oacc[dt][3] * inv1);
        }
        __syncthreads();   // Q/K/V smem safe to overwrite in next pass
    }
}

// ---------------- launch ------------------------------------------------------
extern "C" void kernel_launch(void* const* d_in, const int* in_sizes, int n_in,
                              void* d_out, int out_size) {
    const float* x   = (const float*)d_in[0];
    const float* g1  = (const float*)d_in[1];
    const float* g2  = (const float*)d_in[2];
    const float* w_q = (const float*)d_in[3];
    const float* w_k = (const float*)d_in[4];
    const float* w_v = (const float*)d_in[5];
    const float* w_o = (const float*)d_in[6];
    const float* w1  = (const float*)d_in[7];
    const float* w2  = (const float*)d_in[8];
    const float* w3  = (const float*)d_in[9];
    float* out = (float*)d_out;

    __half *xn, *qkv, *ap, *hn, *f3, *wqkvT, *woT, *w1T, *w3T, *w2T;
    float *hres;
    cudaGetSymbolAddress((void**)&xn,    g_xn);
    cudaGetSymbolAddress((void**)&qkv,   g_qkv);
    cudaGetSymbolAddress((void**)&ap,    g_attn);
    cudaGetSymbolAddress((void**)&hres,  g_hres);
    cudaGetSymbolAddress((void**)&hn,    g_hn);
    cudaGetSymbolAddress((void**)&f3,    g_f3);
    cudaGetSymbolAddress((void**)&wqkvT, g_wqkvT);
    cudaGetSymbolAddress((void**)&woT,   g_woT);
    cudaGetSymbolAddress((void**)&w1T,   g_w1T);
    cudaGetSymbolAddress((void**)&w3T,   g_w3T);
    cudaGetSymbolAddress((void**)&w2T,   g_w2T);

    cudaFuncSetAttribute(gemm_mma<0>, cudaFuncAttributeMaxDynamicSharedMemorySize, GSMEM);
    cudaFuncSetAttribute(gemm_mma<1>, cudaFuncAttributeMaxDynamicSharedMemorySize, GSMEM);
    cudaFuncSetAttribute(gemm_ffn, cudaFuncAttributeMaxDynamicSharedMemorySize, GSMEM);
    cudaFuncSetAttribute(attn_mma, cudaFuncAttributeMaxDynamicSharedMemorySize, ASMEM);

    // merged weight transpose: all 7 weights in one launch
    TransAll ja;
    const float* srcs[7] = { w_q, w_k, w_v, w_o, w1, w3, w2 };
    __half* dsts[7] = { wqkvT, wqkvT + DM*DM, wqkvT + 2*DM*DM, woT, w1T, w3T, w2T };
    int Rs[7] = { DM, DM, DM, DM, DM, DM, DFF };
    int Cs[7] = { DM, DM, DM, DM, DFF, DFF, DM };
    int cum = 0;
    for (int i = 0; i < 7; i++) {
        ja.src[i] = srcs[i]; ja.dst[i] = dsts[i];
        ja.R[i] = Rs[i]; ja.C[i] = Cs[i];
        ja.start[i] = cum;
        cum += (Rs[i] / 32) * (Cs[i] / 32);
    }
    ja.start[7] = cum;
    transpose_all_k<<<cum, 256>>>(ja);

    dim3 gQKV(QKVS / 128, MM / 128);               // (24, 32)
    dim3 gD(DM / 128, MM / 128);                   // (8, 32)
    dim3 gFF(DFF / 64, MM / 128);                  // (43, 32)

    // 1. norm1 -> fp16
    rmsnorm_h<<<MM, 256>>>(x, g1, xn);
    // 2. fused qkv projection -> fp16
    gemm_mma<0><<<gQKV, 256, GSMEM>>>(xn, wqkvT, nullptr, qkv, MM, QKVS, DM);
    // 3. causal flash attention -> fp16 (paired Q tiles, balanced wave)
    attn_mma<<<dim3(8, NH, BB), 256, ASMEM>>>(qkv, ap);
    // 4. h_res = x + attn @ w_o  (fp32)
    gemm_mma<1><<<gD, 256, GSMEM>>>(ap, woT, x, hres, MM, DM, DM);
    // 5. norm2 -> fp16
    rmsnorm_h<<<MM, 256>>>(hres, g2, hn);
    // 6+7. fused f3 = silu(hn @ w1) * (hn @ w3) -> fp16
    gemm_ffn<<<gFF, 256, GSMEM>>>(hn, w1T, w3T, f3, DM);
    // 8. out = h_res + f3 @ w2  (fp32)
    gemm_mma<1><<<gD, 256, GSMEM>>>(f3, w2T, hres, out, MM, DM, DFF);
}